// round 6
// baseline (speedup 1.0000x reference)
#include <cuda_runtime.h>
#include <cstdint>

// NonLocalBlock B=8, N=4096, M=2048, C=256, d=128
#define NB 8
#define NN 4096
#define NM 2048
#define NC 256
#define ND 128

// __device__ scratch (allocation-free rule). ~80 MB.
__device__ float g_theta[NB * NN * ND];
__device__ float g_phi  [NB * NN * ND];
__device__ float g_gg   [NB * NN * ND];
__device__ float g_phiP [NB * NM * ND];          // [b][m][d]
__device__ float g_gPt  [NB * ND * NM];          // [b][d][m]
__device__ float g_y    [NB * NN * ND];

// ---------------------------------------------------------------------------
// TF32 helpers
// ---------------------------------------------------------------------------
__device__ __forceinline__ uint32_t f2tf32(float v) {
    uint32_t r;
    asm("cvt.rna.tf32.f32 %0, %1;" : "=r"(r) : "f"(v));
    return r;
}
__device__ __forceinline__ void mma_tf32(float (&d)[4],
                                         uint32_t a0, uint32_t a1, uint32_t a2, uint32_t a3,
                                         uint32_t b0, uint32_t b1) {
    asm volatile(
        "mma.sync.aligned.m16n8k8.row.col.f32.tf32.tf32.f32 "
        "{%0,%1,%2,%3}, {%4,%5,%6,%7}, {%8,%9}, {%0,%1,%2,%3};"
        : "+f"(d[0]), "+f"(d[1]), "+f"(d[2]), "+f"(d[3])
        : "r"(a0), "r"(a1), "r"(a2), "r"(a3), "r"(b0), "r"(b1));
}

// ---------------------------------------------------------------------------
// Projection GEMM (fp32 SIMT): [32768,256]@[256,128] for 3 weights
// ---------------------------------------------------------------------------
__global__ __launch_bounds__(256) void proj_kernel(
    const float* __restrict__ x, const float* __restrict__ Wt,
    const float* __restrict__ Wp, const float* __restrict__ Wg)
{
    __shared__ float As[32][65];
    __shared__ float Ws[32][ND];
    const float* W; float* out;
    if (blockIdx.z == 0)      { W = Wt; out = g_theta; }
    else if (blockIdx.z == 1) { W = Wp; out = g_phi; }
    else                      { W = Wg; out = g_gg; }
    int tid = threadIdx.x, row0 = blockIdx.x * 64;
    int rg = tid & 15, cg = tid >> 4;
    float acc[4][8];
#pragma unroll
    for (int i = 0; i < 4; i++)
#pragma unroll
        for (int j = 0; j < 8; j++) acc[i][j] = 0.f;
    for (int k0 = 0; k0 < NC; k0 += 32) {
#pragma unroll
        for (int q = 0; q < 2; q++) {
            int li = q * 256 + tid, m = li >> 3, kk = (li & 7) * 4;
            float4 v = *(const float4*)(x + (row0 + m) * NC + k0 + kk);
            As[kk][m] = v.x; As[kk + 1][m] = v.y; As[kk + 2][m] = v.z; As[kk + 3][m] = v.w;
        }
#pragma unroll
        for (int q = 0; q < 4; q++) {
            int li = q * 256 + tid, kk = li >> 5, c4 = (li & 31) * 4;
            *(float4*)&Ws[kk][c4] = *(const float4*)(W + (k0 + kk) * ND + c4);
        }
        __syncthreads();
#pragma unroll
        for (int k = 0; k < 32; k++) {
            float a[4];
#pragma unroll
            for (int i = 0; i < 4; i++) a[i] = As[k][rg + 16 * i];
            float4 w0 = *(float4*)&Ws[k][cg * 8];
            float4 w1 = *(float4*)&Ws[k][cg * 8 + 4];
#pragma unroll
            for (int i = 0; i < 4; i++) {
                acc[i][0] += a[i] * w0.x; acc[i][1] += a[i] * w0.y;
                acc[i][2] += a[i] * w0.z; acc[i][3] += a[i] * w0.w;
                acc[i][4] += a[i] * w1.x; acc[i][5] += a[i] * w1.y;
                acc[i][6] += a[i] * w1.z; acc[i][7] += a[i] * w1.w;
            }
        }
        __syncthreads();
    }
#pragma unroll
    for (int i = 0; i < 4; i++) {
        int r = row0 + rg + 16 * i;
        *(float4*)(out + r * ND + cg * 8)     = make_float4(acc[i][0], acc[i][1], acc[i][2], acc[i][3]);
        *(float4*)(out + r * ND + cg * 8 + 4) = make_float4(acc[i][4], acc[i][5], acc[i][6], acc[i][7]);
    }
}

// ---------------------------------------------------------------------------
// MaxPool(2): phi -> phiP (row-major), g -> gPt (transposed [b][d][m])
// ---------------------------------------------------------------------------
__global__ __launch_bounds__(256) void pool_kernel()
{
    int idx4 = blockIdx.x * 256 + threadIdx.x;
    int total4 = NB * NM * ND / 4;
    if (idx4 >= total4) return;
    int d4 = idx4 % (ND / 4);
    int r  = (idx4 / (ND / 4)) % NM;
    int b  = idx4 / ((ND / 4) * NM);
    int src = ((b * NN + 2 * r) * ND) / 4 + d4;
    const float4* p = (const float4*)g_phi;
    const float4* g = (const float4*)g_gg;
    float4 a = p[src], a2 = p[src + ND / 4];
    float4 c = g[src], c2 = g[src + ND / 4];
    ((float4*)g_phiP)[idx4] = make_float4(fmaxf(a.x, a2.x), fmaxf(a.y, a2.y),
                                          fmaxf(a.z, a2.z), fmaxf(a.w, a2.w));
    int d0 = d4 * 4;
    g_gPt[(b * ND + d0 + 0) * NM + r] = fmaxf(c.x, c2.x);
    g_gPt[(b * ND + d0 + 1) * NM + r] = fmaxf(c.y, c2.y);
    g_gPt[(b * ND + d0 + 2) * NM + r] = fmaxf(c.z, c2.z);
    g_gPt[(b * ND + d0 + 3) * NM + r] = fmaxf(c.w, c2.w);
}

// ---------------------------------------------------------------------------
// Fused flash attention: per CTA 128 q-rows, loop m-chunks of 128.
//   S = theta @ phiP^T (3xTF32 HMMA) -> online softmax -> Y += P @ G (1xTF32)
// 256 threads = 8 warps (4 row-groups x 2 col-groups), warp tile 32 x 64.
// smem (floats): Qs 128x132 | Ps 128x132 | KG 128x68 | stats 7x128
// ---------------------------------------------------------------------------
#define QSTR 132
#define KSTR 68
#define OFF_PS (128 * QSTR)
#define OFF_KG (2 * 128 * QSTR)
#define OFF_ST (2 * 128 * QSTR + 128 * KSTR)
#define ATTN_SMEM_FLOATS (OFF_ST + 7 * 128)

__global__ __launch_bounds__(256, 1) void attn_kernel()
{
    extern __shared__ float sm[];
    float* Qs    = sm;
    float* Ps    = sm + OFF_PS;
    float* KG    = sm + OFF_KG;
    float* rowm  = sm + OFF_ST;
    float* rowl  = rowm + 128;
    float* scal  = rowl + 128;
    float* cmax  = scal + 128;     // [2][128]
    float* csum  = cmax + 256;     // [2][128]

    int tid = threadIdx.x;
    int b = blockIdx.y, q0 = blockIdx.x * 128;
    const float* Qp = g_theta + (size_t)(b * NN + q0) * ND;
    const float* Kp = g_phiP + (size_t)b * NM * ND;
    const float* Gp = g_gPt  + (size_t)b * ND * NM;

    int lane = tid & 31, g = lane >> 2, t = lane & 3;
    int wid = tid >> 5, wr = wid >> 1, wc = wid & 1;
    int r0 = wr * 32, c0 = wc * 64;

    // Stage Q tile 128x128 (fp32)
#pragma unroll
    for (int q = 0; q < 16; q++) {
        int li = q * 256 + tid, r = li >> 5, c = (li & 31) * 4;
        *(float4*)&Qs[r * QSTR + c] = *(const float4*)(Qp + r * ND + c);
    }
    if (tid < 128) { rowm[tid] = -1e30f; rowl[tid] = 0.f; }

    float yacc[2][8][4];
#pragma unroll
    for (int mt = 0; mt < 2; mt++)
#pragma unroll
        for (int nt = 0; nt < 8; nt++)
#pragma unroll
            for (int i = 0; i < 4; i++) yacc[mt][nt][i] = 0.f;

#pragma unroll 1
    for (int ch = 0; ch < 16; ch++) {
        int m0 = ch * 128;
        float sacc[2][8][4];
#pragma unroll
        for (int mt = 0; mt < 2; mt++)
#pragma unroll
            for (int nt = 0; nt < 8; nt++)
#pragma unroll
                for (int i = 0; i < 4; i++) sacc[mt][nt][i] = 0.f;

        // ---- Phase A: S = Q @ K^T over 2 k-halves of 64 ----
#pragma unroll 1
        for (int kc = 0; kc < 2; kc++) {
            int k0 = kc * 64;
            __syncthreads();   // KG reuse guard
#pragma unroll
            for (int q = 0; q < 8; q++) {
                int li = q * 256 + tid, r = li >> 4, c = (li & 15) * 4;
                *(float4*)&KG[r * KSTR + c] = *(const float4*)(Kp + (size_t)(m0 + r) * ND + k0 + c);
            }
            __syncthreads();
#pragma unroll 2
            for (int kst = 0; kst < 8; kst++) {
                int kk = kst * 8;
                uint32_t ah[2][4], al[2][4];
#pragma unroll
                for (int mt = 0; mt < 2; mt++) {
                    const float* ab = Qs + (r0 + 16 * mt + g) * QSTR + k0 + kk + t;
                    float v0 = ab[0], v1 = ab[8 * QSTR], v2 = ab[4], v3 = ab[8 * QSTR + 4];
                    ah[mt][0] = f2tf32(v0); al[mt][0] = f2tf32(v0 - __uint_as_float(ah[mt][0]));
                    ah[mt][1] = f2tf32(v1); al[mt][1] = f2tf32(v1 - __uint_as_float(ah[mt][1]));
                    ah[mt][2] = f2tf32(v2); al[mt][2] = f2tf32(v2 - __uint_as_float(ah[mt][2]));
                    ah[mt][3] = f2tf32(v3); al[mt][3] = f2tf32(v3 - __uint_as_float(ah[mt][3]));
                }
#pragma unroll
                for (int nt = 0; nt < 8; nt++) {
                    const float* kb = KG + (c0 + 8 * nt + g) * KSTR + kk + t;
                    float w0 = kb[0], w1 = kb[4];
                    uint32_t bh0 = f2tf32(w0), bh1 = f2tf32(w1);
                    uint32_t bl0 = f2tf32(w0 - __uint_as_float(bh0));
                    uint32_t bl1 = f2tf32(w1 - __uint_as_float(bh1));
#pragma unroll
                    for (int mt = 0; mt < 2; mt++) {
                        mma_tf32(sacc[mt][nt], ah[mt][0], ah[mt][1], ah[mt][2], ah[mt][3], bh0, bh1);
                        mma_tf32(sacc[mt][nt], ah[mt][0], ah[mt][1], ah[mt][2], ah[mt][3], bl0, bl1);
                        mma_tf32(sacc[mt][nt], al[mt][0], al[mt][1], al[mt][2], al[mt][3], bh0, bh1);
                    }
                }
            }
        }

        // ---- Phase B: online softmax ----
        // per-warp row max -> cmax[wc]
#pragma unroll
        for (int mt = 0; mt < 2; mt++) {
            float mx0 = -1e30f, mx1 = -1e30f;
#pragma unroll
            for (int nt = 0; nt < 8; nt++) {
                mx0 = fmaxf(mx0, fmaxf(sacc[mt][nt][0], sacc[mt][nt][1]));
                mx1 = fmaxf(mx1, fmaxf(sacc[mt][nt][2], sacc[mt][nt][3]));
            }
            mx0 = fmaxf(mx0, __shfl_xor_sync(0xFFFFFFFF, mx0, 1));
            mx0 = fmaxf(mx0, __shfl_xor_sync(0xFFFFFFFF, mx0, 2));
            mx1 = fmaxf(mx1, __shfl_xor_sync(0xFFFFFFFF, mx1, 1));
            mx1 = fmaxf(mx1, __shfl_xor_sync(0xFFFFFFFF, mx1, 2));
            if (t == 0) {
                cmax[wc * 128 + r0 + 16 * mt + g]     = mx0;
                cmax[wc * 128 + r0 + 16 * mt + g + 8] = mx1;
            }
        }
        __syncthreads();
        if (tid < 128) {
            float nm = fmaxf(rowm[tid], fmaxf(cmax[tid], cmax[128 + tid]));
            scal[tid] = __expf(rowm[tid] - nm);
            rowm[tid] = nm;
        }
        __syncthreads();
        // P = exp(S - nm), row-sum partials, write P to Ps, rescale Y
#pragma unroll
        for (int mt = 0; mt < 2; mt++) {
            int ra = r0 + 16 * mt + g, rb = ra + 8;
            float nma = rowm[ra], nmb = rowm[rb];
            float sum0 = 0.f, sum1 = 0.f;
#pragma unroll
            for (int nt = 0; nt < 8; nt++) {
                float p0 = __expf(sacc[mt][nt][0] - nma);
                float p1 = __expf(sacc[mt][nt][1] - nma);
                float p2 = __expf(sacc[mt][nt][2] - nmb);
                float p3 = __expf(sacc[mt][nt][3] - nmb);
                sum0 += p0 + p1; sum1 += p2 + p3;
                int cc = c0 + 8 * nt + 2 * t;
                *(float2*)&Ps[ra * QSTR + cc] = make_float2(p0, p1);
                *(float2*)&Ps[rb * QSTR + cc] = make_float2(p2, p3);
            }
            sum0 += __shfl_xor_sync(0xFFFFFFFF, sum0, 1);
            sum0 += __shfl_xor_sync(0xFFFFFFFF, sum0, 2);
            sum1 += __shfl_xor_sync(0xFFFFFFFF, sum1, 1);
            sum1 += __shfl_xor_sync(0xFFFFFFFF, sum1, 2);
            if (t == 0) {
                csum[wc * 128 + ra] = sum0;
                csum[wc * 128 + rb] = sum1;
            }
            float sa = scal[ra], sb = scal[rb];
#pragma unroll
            for (int nt = 0; nt < 8; nt++) {
                yacc[mt][nt][0] *= sa; yacc[mt][nt][1] *= sa;
                yacc[mt][nt][2] *= sb; yacc[mt][nt][3] *= sb;
            }
        }
        __syncthreads();
        if (tid < 128)
            rowl[tid] = rowl[tid] * scal[tid] + csum[tid] + csum[128 + tid];

        // ---- Phase C: Y += P @ G over 2 m-halves of 64 ----
#pragma unroll 1
        for (int hc = 0; hc < 2; hc++) {
            int mh = hc * 64;
            __syncthreads();
#pragma unroll
            for (int q = 0; q < 8; q++) {
                int li = q * 256 + tid, r = li >> 4, c = (li & 15) * 4;
                *(float4*)&KG[r * KSTR + c] = *(const float4*)(Gp + (size_t)r * NM + m0 + mh + c);
            }
            __syncthreads();
#pragma unroll 2
            for (int kst = 0; kst < 8; kst++) {
                int kk = kst * 8;
                uint32_t a[2][4];
#pragma unroll
                for (int mt = 0; mt < 2; mt++) {
                    const float* ab = Ps + (r0 + 16 * mt + g) * QSTR + mh + kk + t;
                    a[mt][0] = f2tf32(ab[0]);
                    a[mt][1] = f2tf32(ab[8 * QSTR]);
                    a[mt][2] = f2tf32(ab[4]);
                    a[mt][3] = f2tf32(ab[8 * QSTR + 4]);
                }
#pragma unroll
                for (int nt = 0; nt < 8; nt++) {
                    const float* gb = KG + (c0 + 8 * nt + g) * KSTR + kk + t;
                    uint32_t b0 = f2tf32(gb[0]), b1 = f2tf32(gb[4]);
#pragma unroll
                    for (int mt = 0; mt < 2; mt++)
                        mma_tf32(yacc[mt][nt], a[mt][0], a[mt][1], a[mt][2], a[mt][3], b0, b1);
                }
            }
        }
    }

    __syncthreads();
    // Normalize by rowl and store Y
#pragma unroll
    for (int mt = 0; mt < 2; mt++) {
        int ra = r0 + 16 * mt + g, rb = ra + 8;
        float ia = 1.f / rowl[ra], ib = 1.f / rowl[rb];
        float* Yo0 = g_y + (size_t)(b * NN + q0 + ra) * ND + c0;
        float* Yo1 = g_y + (size_t)(b * NN + q0 + rb) * ND + c0;
#pragma unroll
        for (int nt = 0; nt < 8; nt++) {
            *(float2*)(Yo0 + 8 * nt + 2 * t) = make_float2(yacc[mt][nt][0] * ia, yacc[mt][nt][1] * ia);
            *(float2*)(Yo1 + 8 * nt + 2 * t) = make_float2(yacc[mt][nt][2] * ib, yacc[mt][nt][3] * ib);
        }
    }
}

// ---------------------------------------------------------------------------
// Output GEMM + residual (fp32 SIMT)
// ---------------------------------------------------------------------------
__global__ __launch_bounds__(256) void out_kernel(
    const float* __restrict__ x, const float* __restrict__ Wout, float* __restrict__ out)
{
    __shared__ float As[32][65];
    __shared__ float Ws[32][128];
    int tid = threadIdx.x, row0 = blockIdx.x * 64, col0 = blockIdx.y * 128;
    int rg = tid & 15, cg = tid >> 4;
    float acc[4][8];
#pragma unroll
    for (int i = 0; i < 4; i++)
#pragma unroll
        for (int j = 0; j < 8; j++) acc[i][j] = 0.f;
    for (int k0 = 0; k0 < ND; k0 += 32) {
#pragma unroll
        for (int q = 0; q < 2; q++) {
            int li = q * 256 + tid, m = li >> 3, kk = (li & 7) * 4;
            float4 v = *(const float4*)(g_y + (row0 + m) * ND + k0 + kk);
            As[kk][m] = v.x; As[kk + 1][m] = v.y; As[kk + 2][m] = v.z; As[kk + 3][m] = v.w;
        }
#pragma unroll
        for (int q = 0; q < 4; q++) {
            int li = q * 256 + tid, kk = li >> 5, c4 = (li & 31) * 4;
            *(float4*)&Ws[kk][c4] = *(const float4*)(Wout + (k0 + kk) * NC + col0 + c4);
        }
        __syncthreads();
#pragma unroll
        for (int k = 0; k < 32; k++) {
            float a[4];
#pragma unroll
            for (int i = 0; i < 4; i++) a[i] = As[k][rg + 16 * i];
            float4 w0 = *(float4*)&Ws[k][cg * 8];
            float4 w1 = *(float4*)&Ws[k][cg * 8 + 4];
#pragma unroll
            for (int i = 0; i < 4; i++) {
                acc[i][0] += a[i] * w0.x; acc[i][1] += a[i] * w0.y;
                acc[i][2] += a[i] * w0.z; acc[i][3] += a[i] * w0.w;
                acc[i][4] += a[i] * w1.x; acc[i][5] += a[i] * w1.y;
                acc[i][6] += a[i] * w1.z; acc[i][7] += a[i] * w1.w;
            }
        }
        __syncthreads();
    }
#pragma unroll
    for (int i = 0; i < 4; i++) {
        int r = row0 + rg + 16 * i;
        const float* xr = x + r * NC + col0 + cg * 8;
        float* orow = out + r * NC + col0 + cg * 8;
        float4 x0 = *(const float4*)xr, x1 = *(const float4*)(xr + 4);
        *(float4*)orow = make_float4(acc[i][0] + x0.x, acc[i][1] + x0.y,
                                     acc[i][2] + x0.z, acc[i][3] + x0.w);
        *(float4*)(orow + 4) = make_float4(acc[i][4] + x1.x, acc[i][5] + x1.y,
                                           acc[i][6] + x1.z, acc[i][7] + x1.w);
    }
}

// ---------------------------------------------------------------------------
extern "C" void kernel_launch(void* const* d_in, const int* in_sizes, int n_in,
                              void* d_out, int out_size)
{
    const float* x  = (const float*)d_in[0];
    const float* Wt = (const float*)d_in[1];
    const float* Wp = (const float*)d_in[2];
    const float* Wg = (const float*)d_in[3];
    const float* Wo = (const float*)d_in[4];
    float* out      = (float*)d_out;

    const int ATTN_SMEM = ATTN_SMEM_FLOATS * 4;   // 173568 B
    cudaFuncSetAttribute(attn_kernel, cudaFuncAttributeMaxDynamicSharedMemorySize, ATTN_SMEM);

    proj_kernel<<<dim3(512, 1, 3), 256>>>(x, Wt, Wp, Wg);
    pool_kernel<<<(NB * NM * ND / 4 + 255) / 256, 256>>>();
    attn_kernel<<<dim3(32, 8), 256, ATTN_SMEM>>>();
    out_kernel<<<dim3(512, 2), 256>>>(x, Wo, out);
}